// round 3
// baseline (speedup 1.0000x reference)
#include <cuda_runtime.h>
#include <cuda.h>
#include <cstdint>
#include <dlfcn.h>

// ============================================================================
// out = x @ (W + 2*B@A)^T ; x:[8192,4096] f32, W:[4096,4096] f32
// Plain sm_100 (no tcgen05). tf32 mma.sync m16n8k8, CTA tile 128x256,
// 4-stage TMA pipeline, 8 compute warps (64x64 each) + 1 producer warp.
// R3: ldmatrix.x4 fragment loads (8 LDSM vs 32 LDS per kk) + double-buffered
//     fragments; float4 prep_w.
// ============================================================================

static constexpr int M_ALL = 8192;
static constexpr int N_ALL = 4096;
static constexpr int K_ALL = 4096;
static constexpr int MT = 128;
static constexpr int NT = 256;
static constexpr int KC = 32;                 // K floats per stage
static constexpr int STAGES = 4;
static constexpr int KITERS = K_ALL / KC;     // 128
static constexpr int A_BYTES = MT * KC * 4;   // 16384
static constexpr int B_BYTES = NT * KC * 4;   // 32768
static constexpr int STAGE_BYTES = A_BYTES + B_BYTES;          // 49152
static constexpr int SMEM_TILE0 = 1024;
static constexpr int SMEM_TOTAL = SMEM_TILE0 + STAGES * STAGE_BYTES; // 197632

static constexpr int MB_FULL = 0;    // 4 x 8B
static constexpr int MB_EMPTY = 64;  // 4 x 8B

__device__ __align__(1024) float g_weff[16777216]; // 64 MB
__device__ __align__(1024) float g_xr[33554432];   // 128 MB

// ---------------------------------------------------------------------------
__device__ __forceinline__ uint32_t smem_u32(const void* p) {
    uint32_t a;
    asm("{ .reg .u64 t; cvta.to.shared.u64 t, %1; cvt.u32.u64 %0, t; }" : "=r"(a) : "l"(p));
    return a;
}
__device__ __forceinline__ uint32_t elect_one() {
    uint32_t p;
    asm volatile("{\n\t.reg .pred p;\n\telect.sync _|p, 0xFFFFFFFF;\n\tselp.b32 %0, 1, 0, p;\n\t}" : "=r"(p));
    return p;
}
__device__ __forceinline__ float f2tf32(float v) {
    uint32_t u;
    asm("cvt.rna.tf32.f32 %0, %1;" : "=r"(u) : "f"(v));
    return __uint_as_float(u);
}

#define MBARRIER_INIT(addr, cnt) \
    asm volatile("mbarrier.init.shared.b64 [%0], %1;" :: "r"((uint32_t)(addr)), "r"((uint32_t)(cnt)) : "memory")
#define MBARRIER_EXPECT_TX(addr, bytes) \
    asm volatile("mbarrier.arrive.expect_tx.shared.b64 _, [%0], %1;" :: "r"((uint32_t)(addr)), "r"((uint32_t)(bytes)) : "memory")
#define MBARRIER_ARRIVE(addr) \
    asm volatile("mbarrier.arrive.shared.b64 _, [%0];" :: "r"((uint32_t)(addr)) : "memory")

#define MBARRIER_WAIT_PARITY(mbar_smem_addr, phase_parity) do { \
    uint32_t _mbar = (uint32_t)(mbar_smem_addr); \
    uint32_t _parity = (uint32_t)(phase_parity); \
    uint32_t _done; \
    asm volatile( \
        "{\n\t.reg .pred p;\n\t" \
        "mbarrier.try_wait.parity.acquire.cta.shared::cta.b64 p, [%1], %2;\n\t" \
        "selp.b32 %0, 1, 0, p;\n\t}" \
        : "=r"(_done) : "r"(_mbar), "r"(_parity) : "memory"); \
    if (!_done) { \
        asm volatile( \
            "{\n\t.reg .pred P1;\n\t" \
            "WAIT_LOOP_%=:\n\t" \
            "mbarrier.try_wait.parity.acquire.cta.shared::cta.b64 P1, [%0], %1, 0x989680;\n\t" \
            "@P1 bra.uni WAIT_DONE_%=;\n\t" \
            "bra.uni WAIT_LOOP_%=;\n\t" \
            "WAIT_DONE_%=:\n\t}" \
            :: "r"(_mbar), "r"(_parity) : "memory"); \
    } \
} while (0)

__device__ __forceinline__ void tma_load_2d(uint32_t smem_addr, const CUtensorMap* tm,
                                            int cx, int cy, uint32_t mbar) {
    asm volatile(
        "cp.async.bulk.tensor.2d.shared::cta.global.tile.mbarrier::complete_tx::bytes "
        "[%0], [%1, {%2, %3}], [%4];"
        :: "r"(smem_addr), "l"(tm), "r"(cx), "r"(cy), "r"(mbar) : "memory");
}

__device__ __forceinline__ void mma_tf32(float* d, const uint32_t* a, uint32_t b0, uint32_t b1) {
    asm("mma.sync.aligned.m16n8k8.row.col.f32.tf32.tf32.f32 "
        "{%0,%1,%2,%3}, {%4,%5,%6,%7}, {%8,%9}, {%0,%1,%2,%3};"
        : "+f"(d[0]), "+f"(d[1]), "+f"(d[2]), "+f"(d[3])
        : "r"(a[0]), "r"(a[1]), "r"(a[2]), "r"(a[3]), "r"(b0), "r"(b1));
}

// ldmatrix x4: 4 8x8 b16 matrices. For f32 data, one x4 = a 16-row x 8-f32-col
// tile (two 16B chunks per row): lanes 0-15 supply rows 0-15 at chunk c,
// lanes 16-31 supply rows 0-15 at chunk c+1. Delivery: reg m = matrix m at
// [lane/4][lane%4] (f32 granularity) -> exactly the m16n8k8 fragment layout.
__device__ __forceinline__ void ldsm4(uint32_t* r, uint32_t addr) {
    asm volatile("ldmatrix.sync.aligned.m8n8.x4.shared.b16 {%0,%1,%2,%3}, [%4];"
        : "=r"(r[0]), "=r"(r[1]), "=r"(r[2]), "=r"(r[3]) : "r"(addr));
}

// ---------------------------------------------------------------------------
__global__ void prep_x(const float* __restrict__ x) {
    int i = blockIdx.x * blockDim.x + threadIdx.x;
    float4 v = reinterpret_cast<const float4*>(x)[i];
    float4 o;
    o.x = f2tf32(v.x); o.y = f2tf32(v.y); o.z = f2tf32(v.z); o.w = f2tf32(v.w);
    reinterpret_cast<float4*>(g_xr)[i] = o;
}

__global__ void prep_w(const float* __restrict__ W, const float* __restrict__ lA,
                       const float* __restrict__ lB) {
    __shared__ float sB[16];
    int n = blockIdx.x;
    if (threadIdx.x < 16) sB[threadIdx.x] = 2.0f * lB[n * 16 + threadIdx.x];
    __syncthreads();
    const float4* W4 = reinterpret_cast<const float4*>(W + (size_t)n * K_ALL);
    float4* O4 = reinterpret_cast<float4*>(g_weff + (size_t)n * K_ALL);
    for (int k4 = threadIdx.x; k4 < K_ALL / 4; k4 += blockDim.x) {
        float4 acc = W4[k4];
        #pragma unroll
        for (int r = 0; r < 16; r++) {
            float4 a = reinterpret_cast<const float4*>(lA + (size_t)r * K_ALL)[k4];
            acc.x = fmaf(sB[r], a.x, acc.x);
            acc.y = fmaf(sB[r], a.y, acc.y);
            acc.z = fmaf(sB[r], a.z, acc.z);
            acc.w = fmaf(sB[r], a.w, acc.w);
        }
        acc.x = f2tf32(acc.x); acc.y = f2tf32(acc.y);
        acc.z = f2tf32(acc.z); acc.w = f2tf32(acc.w);
        O4[k4] = acc;
    }
}

// ---------------------------------------------------------------------------
// GEMM. smem tiles: [rows][32 f32] rows of 128B, TMA SW128: 16B-chunk j of
// row r lands at chunk j ^ (r&7). warps 0-7 compute (2x4, 64x64), warp 8 TMA.
// ---------------------------------------------------------------------------
__global__ void __launch_bounds__(288, 1)
gemm_tf32(const __grid_constant__ CUtensorMap tmA,
          const __grid_constant__ CUtensorMap tmB,
          float* __restrict__ out) {
    extern __shared__ char smem[];
    uint32_t sb = smem_u32(smem);
    const int tid = threadIdx.x, wid = tid >> 5, lane = tid & 31;
    const int mtile = blockIdx.y, ntile = blockIdx.x;

    if (tid == 0) {
        #pragma unroll
        for (int s = 0; s < STAGES; s++) {
            MBARRIER_INIT(sb + MB_FULL + 8 * s, 1);
            MBARRIER_INIT(sb + MB_EMPTY + 8 * s, 256);
        }
        asm volatile("fence.proxy.async.shared::cta;" ::: "memory");
    }
    __syncthreads();

    if (wid == 8) {
        // ---------------- producer ----------------
        if (elect_one()) {
            int st = 0, ph = 1;
            for (int k = 0; k < KITERS; k++) {
                MBARRIER_WAIT_PARITY(sb + MB_EMPTY + 8 * st, ph);
                MBARRIER_EXPECT_TX(sb + MB_FULL + 8 * st, STAGE_BYTES);
                uint32_t abase = sb + SMEM_TILE0 + st * STAGE_BYTES;
                tma_load_2d(abase, &tmA, k * KC, mtile * MT, sb + MB_FULL + 8 * st);
                tma_load_2d(abase + A_BYTES, &tmB, k * KC, ntile * NT, sb + MB_FULL + 8 * st);
                if (++st == STAGES) { st = 0; ph ^= 1; }
            }
        }
        return;
    }

    // ---------------- compute warps ----------------
    const int mw = (wid >> 2) * 64;   // 0 / 64
    const int nw = (wid & 3) * 64;    // 0..192
    const int g = lane >> 2;          // row within 8
    const int q = lane & 3;           // f32 col within 4
    const int rlane = lane & 15;      // ldsm source row
    const uint32_t cc = (lane >> 4) & 1;  // ldsm chunk half
    const uint32_t xr = (uint32_t)(lane & 7); // swizzle xor (row&7)

    // ldsm row-base offsets (relative to CTA smem base), per fragment
    uint32_t offA[4], offB[4];
    #pragma unroll
    for (int tm = 0; tm < 4; tm++)
        offA[tm] = (uint32_t)(SMEM_TILE0 + (mw + tm * 16 + rlane) * 128);
    #pragma unroll
    for (int p = 0; p < 4; p++)
        offB[p] = (uint32_t)(SMEM_TILE0 + A_BYTES + (nw + p * 16 + rlane) * 128);

    float acc[4][8][4];
    #pragma unroll
    for (int tm = 0; tm < 4; tm++)
        #pragma unroll
        for (int tn = 0; tn < 8; tn++)
            #pragma unroll
            for (int r = 0; r < 4; r++) acc[tm][tn][r] = 0.0f;

    uint32_t fa[2][4][4], fb[2][4][4];

    int st = 0, ph = 0;
    for (int k = 0; k < KITERS; k++) {
        MBARRIER_WAIT_PARITY(sb + MB_FULL + 8 * st, ph);
        const uint32_t sbase = sb + (uint32_t)(st * STAGE_BYTES);

        // load kk=0 fragments into buffer 0
        {
            const uint32_t co = ((0u + cc) ^ xr) << 4;   // chunk (2*0+cc)^xr
            #pragma unroll
            for (int tm = 0; tm < 4; tm++) ldsm4(fa[0][tm], sbase + offA[tm] + co);
            #pragma unroll
            for (int p = 0; p < 4; p++)    ldsm4(fb[0][p],  sbase + offB[p] + co);
        }

        #pragma unroll
        for (int kk = 0; kk < 4; kk++) {
            const int cur = kk & 1, nxt = cur ^ 1;
            if (kk < 3) {
                const uint32_t co = (((uint32_t)(2 * (kk + 1)) + cc) ^ xr) << 4;
                #pragma unroll
                for (int tm = 0; tm < 4; tm++) ldsm4(fa[nxt][tm], sbase + offA[tm] + co);
                #pragma unroll
                for (int p = 0; p < 4; p++)    ldsm4(fb[nxt][p],  sbase + offB[p] + co);
            }
            #pragma unroll
            for (int tm = 0; tm < 4; tm++) {
                #pragma unroll
                for (int p = 0; p < 4; p++) {
                    mma_tf32(acc[tm][2 * p + 0], fa[cur][tm], fb[cur][p][0], fb[cur][p][2]);
                    mma_tf32(acc[tm][2 * p + 1], fa[cur][tm], fb[cur][p][1], fb[cur][p][3]);
                }
            }
        }

        MBARRIER_ARRIVE(sb + MB_EMPTY + 8 * st);
        if (++st == STAGES) { st = 0; ph ^= 1; }
    }

    // ---------------- epilogue ----------------
    #pragma unroll
    for (int tm = 0; tm < 4; tm++) {
        const int row0 = mtile * MT + mw + tm * 16 + g;
        #pragma unroll
        for (int tn = 0; tn < 8; tn++) {
            const int col = ntile * NT + nw + tn * 8 + 2 * q;
            float2 lo = make_float2(acc[tm][tn][0], acc[tm][tn][1]);
            float2 hi = make_float2(acc[tm][tn][2], acc[tm][tn][3]);
            *reinterpret_cast<float2*>(out + (size_t)row0 * N_ALL + col) = lo;
            *reinterpret_cast<float2*>(out + (size_t)(row0 + 8) * N_ALL + col) = hi;
        }
    }
}

// ---------------------------------------------------------------------------
typedef CUresult (*EncodeFn)(CUtensorMap*, CUtensorMapDataType, cuuint32_t, void*,
                             const cuuint64_t*, const cuuint64_t*, const cuuint32_t*,
                             const cuuint32_t*, CUtensorMapInterleave, CUtensorMapSwizzle,
                             CUtensorMapL2promotion, CUtensorMapFloatOOBfill);

extern "C" void kernel_launch(void* const* d_in, const int* in_sizes, int n_in,
                              void* d_out, int out_size) {
    const float* x  = (const float*)d_in[0];
    const float* W  = (const float*)d_in[1];
    const float* lA = (const float*)d_in[2];
    const float* lB = (const float*)d_in[3];
    float* out = (float*)d_out;

    void* xr = nullptr;
    void* wf = nullptr;
    cudaGetSymbolAddress(&xr, g_xr);
    cudaGetSymbolAddress(&wf, g_weff);

    void* h = dlopen("libcuda.so.1", RTLD_LAZY | RTLD_GLOBAL);
    if (!h) h = dlopen("libcuda.so", RTLD_LAZY | RTLD_GLOBAL);
    EncodeFn enc = h ? (EncodeFn)dlsym(h, "cuTensorMapEncodeTiled") : nullptr;
    if (!enc || !xr || !wf) return;

    CUtensorMap tmA{}, tmB{};
    {
        cuuint64_t dims[2] = {(cuuint64_t)K_ALL, (cuuint64_t)M_ALL};
        cuuint64_t str[1]  = {(cuuint64_t)K_ALL * 4};
        cuuint32_t box[2]  = {(cuuint32_t)KC, (cuuint32_t)MT};
        cuuint32_t es[2]   = {1, 1};
        enc(&tmA, CU_TENSOR_MAP_DATA_TYPE_FLOAT32, 2, xr, dims, str, box, es,
            CU_TENSOR_MAP_INTERLEAVE_NONE, CU_TENSOR_MAP_SWIZZLE_128B,
            CU_TENSOR_MAP_L2_PROMOTION_L2_128B, CU_TENSOR_MAP_FLOAT_OOB_FILL_NONE);
    }
    {
        cuuint64_t dims[2] = {(cuuint64_t)K_ALL, (cuuint64_t)N_ALL};
        cuuint64_t str[1]  = {(cuuint64_t)K_ALL * 4};
        cuuint32_t box[2]  = {(cuuint32_t)KC, (cuuint32_t)NT};
        cuuint32_t es[2]   = {1, 1};
        enc(&tmB, CU_TENSOR_MAP_DATA_TYPE_FLOAT32, 2, wf, dims, str, box, es,
            CU_TENSOR_MAP_INTERLEAVE_NONE, CU_TENSOR_MAP_SWIZZLE_128B,
            CU_TENSOR_MAP_L2_PROMOTION_L2_128B, CU_TENSOR_MAP_FLOAT_OOB_FILL_NONE);
    }

    cudaFuncSetAttribute(gemm_tf32, cudaFuncAttributeMaxDynamicSharedMemorySize, SMEM_TOTAL);

    prep_x<<<(M_ALL * K_ALL / 4) / 256, 256>>>(x);
    prep_w<<<N_ALL, 256>>>(W, lA, lB);

    dim3 grid(N_ALL / NT, M_ALL / MT); // (16, 64)
    gemm_tf32<<<grid, 288, SMEM_TOTAL>>>(tmA, tmB, out);
}

// round 4
// speedup vs baseline: 1.1428x; 1.1428x over previous
#include <cuda_runtime.h>
#include <cuda.h>
#include <cstdint>
#include <dlfcn.h>

// ============================================================================
// out = x @ (W + 2*B@A)^T ; x:[8192,4096] f32, W:[4096,4096] f32
// Plain sm_100 (no tcgen05). tf32 mma.sync m16n8k8, CTA tile 128x256,
// 4-stage TMA pipeline, 8 compute warps (64x64 each) + 1 producer warp.
// R4 = R2 (best: 1379us) + warp-elected mbarrier wait/arrive (32x less
//      barrier MIO traffic in the mainloop) + vectorized prep_w.
// ============================================================================

static constexpr int M_ALL = 8192;
static constexpr int N_ALL = 4096;
static constexpr int K_ALL = 4096;
static constexpr int MT = 128;
static constexpr int NT = 256;
static constexpr int KC = 32;                 // K floats per stage
static constexpr int STAGES = 4;
static constexpr int KITERS = K_ALL / KC;     // 128
static constexpr int A_BYTES = MT * KC * 4;   // 16384
static constexpr int B_BYTES = NT * KC * 4;   // 32768
static constexpr int STAGE_BYTES = A_BYTES + B_BYTES;          // 49152
static constexpr int SMEM_TILE0 = 1024;
static constexpr int SMEM_TOTAL = SMEM_TILE0 + STAGES * STAGE_BYTES; // 197632

static constexpr int MB_FULL = 0;    // 4 x 8B
static constexpr int MB_EMPTY = 64;  // 4 x 8B

__device__ __align__(1024) float g_weff[16777216]; // 64 MB
__device__ __align__(1024) float g_xr[33554432];   // 128 MB

// ---------------------------------------------------------------------------
__device__ __forceinline__ uint32_t smem_u32(const void* p) {
    uint32_t a;
    asm("{ .reg .u64 t; cvta.to.shared.u64 t, %1; cvt.u32.u64 %0, t; }" : "=r"(a) : "l"(p));
    return a;
}
__device__ __forceinline__ uint32_t elect_one() {
    uint32_t p;
    asm volatile("{\n\t.reg .pred p;\n\telect.sync _|p, 0xFFFFFFFF;\n\tselp.b32 %0, 1, 0, p;\n\t}" : "=r"(p));
    return p;
}
__device__ __forceinline__ float f2tf32(float v) {
    uint32_t u;
    asm("cvt.rna.tf32.f32 %0, %1;" : "=r"(u) : "f"(v));
    return __uint_as_float(u);
}
__device__ __forceinline__ uint32_t lds32(uint32_t a) {
    uint32_t v;
    asm volatile("ld.shared.b32 %0, [%1];" : "=r"(v) : "r"(a));
    return v;
}

#define MBARRIER_INIT(addr, cnt) \
    asm volatile("mbarrier.init.shared.b64 [%0], %1;" :: "r"((uint32_t)(addr)), "r"((uint32_t)(cnt)) : "memory")
#define MBARRIER_EXPECT_TX(addr, bytes) \
    asm volatile("mbarrier.arrive.expect_tx.shared.b64 _, [%0], %1;" :: "r"((uint32_t)(addr)), "r"((uint32_t)(bytes)) : "memory")
#define MBARRIER_ARRIVE(addr) \
    asm volatile("mbarrier.arrive.shared.b64 _, [%0];" :: "r"((uint32_t)(addr)) : "memory")

#define MBARRIER_WAIT_PARITY(mbar_smem_addr, phase_parity) do { \
    uint32_t _mbar = (uint32_t)(mbar_smem_addr); \
    uint32_t _parity = (uint32_t)(phase_parity); \
    uint32_t _done; \
    asm volatile( \
        "{\n\t.reg .pred p;\n\t" \
        "mbarrier.try_wait.parity.acquire.cta.shared::cta.b64 p, [%1], %2;\n\t" \
        "selp.b32 %0, 1, 0, p;\n\t}" \
        : "=r"(_done) : "r"(_mbar), "r"(_parity) : "memory"); \
    if (!_done) { \
        asm volatile( \
            "{\n\t.reg .pred P1;\n\t" \
            "WAIT_LOOP_%=:\n\t" \
            "mbarrier.try_wait.parity.acquire.cta.shared::cta.b64 P1, [%0], %1, 0x989680;\n\t" \
            "@P1 bra.uni WAIT_DONE_%=;\n\t" \
            "bra.uni WAIT_LOOP_%=;\n\t" \
            "WAIT_DONE_%=:\n\t}" \
            :: "r"(_mbar), "r"(_parity) : "memory"); \
    } \
} while (0)

__device__ __forceinline__ void tma_load_2d(uint32_t smem_addr, const CUtensorMap* tm,
                                            int cx, int cy, uint32_t mbar) {
    asm volatile(
        "cp.async.bulk.tensor.2d.shared::cta.global.tile.mbarrier::complete_tx::bytes "
        "[%0], [%1, {%2, %3}], [%4];"
        :: "r"(smem_addr), "l"(tm), "r"(cx), "r"(cy), "r"(mbar) : "memory");
}

__device__ __forceinline__ void mma_tf32(float* d, const uint32_t* a, const uint32_t* b) {
    asm("mma.sync.aligned.m16n8k8.row.col.f32.tf32.tf32.f32 "
        "{%0,%1,%2,%3}, {%4,%5,%6,%7}, {%8,%9}, {%0,%1,%2,%3};"
        : "+f"(d[0]), "+f"(d[1]), "+f"(d[2]), "+f"(d[3])
        : "r"(a[0]), "r"(a[1]), "r"(a[2]), "r"(a[3]), "r"(b[0]), "r"(b[1]));
}

// ---------------------------------------------------------------------------
__global__ void prep_x(const float* __restrict__ x) {
    int i = blockIdx.x * blockDim.x + threadIdx.x;
    float4 v = reinterpret_cast<const float4*>(x)[i];
    float4 o;
    o.x = f2tf32(v.x); o.y = f2tf32(v.y); o.z = f2tf32(v.z); o.w = f2tf32(v.w);
    reinterpret_cast<float4*>(g_xr)[i] = o;
}

__global__ void prep_w(const float* __restrict__ W, const float* __restrict__ lA,
                       const float* __restrict__ lB) {
    __shared__ float sB[16];
    int n = blockIdx.x;
    if (threadIdx.x < 16) sB[threadIdx.x] = 2.0f * lB[n * 16 + threadIdx.x];
    __syncthreads();
    const float4* W4 = reinterpret_cast<const float4*>(W + (size_t)n * K_ALL);
    float4* O4 = reinterpret_cast<float4*>(g_weff + (size_t)n * K_ALL);
    for (int k4 = threadIdx.x; k4 < K_ALL / 4; k4 += blockDim.x) {
        float4 acc = W4[k4];
        #pragma unroll
        for (int r = 0; r < 16; r++) {
            float4 a = reinterpret_cast<const float4*>(lA + (size_t)r * K_ALL)[k4];
            acc.x = fmaf(sB[r], a.x, acc.x);
            acc.y = fmaf(sB[r], a.y, acc.y);
            acc.z = fmaf(sB[r], a.z, acc.z);
            acc.w = fmaf(sB[r], a.w, acc.w);
        }
        acc.x = f2tf32(acc.x); acc.y = f2tf32(acc.y);
        acc.z = f2tf32(acc.z); acc.w = f2tf32(acc.w);
        O4[k4] = acc;
    }
}

// ---------------------------------------------------------------------------
// GEMM. smem A tile: [128 rows][32 f32] SW128 (phys col = c ^ ((r&7)*4)).
//       smem B tile: [256 rows][32 f32] same swizzle.
// warps 0-7 compute (2x4 -> warp tile 64x64), warp 8 = TMA producer.
// ---------------------------------------------------------------------------
__global__ void __launch_bounds__(288, 1)
gemm_tf32(const __grid_constant__ CUtensorMap tmA,
          const __grid_constant__ CUtensorMap tmB,
          float* __restrict__ out) {
    extern __shared__ char smem[];
    uint32_t sb = smem_u32(smem);
    const int tid = threadIdx.x, wid = tid >> 5, lane = tid & 31;
    const int mtile = blockIdx.y, ntile = blockIdx.x;

    if (tid == 0) {
        #pragma unroll
        for (int s = 0; s < STAGES; s++) {
            MBARRIER_INIT(sb + MB_FULL + 8 * s, 1);   // producer expect_tx
            MBARRIER_INIT(sb + MB_EMPTY + 8 * s, 8);  // 8 warp-elected arrives
        }
        asm volatile("fence.proxy.async.shared::cta;" ::: "memory");
    }
    __syncthreads();

    if (wid == 8) {
        // ---------------- producer ----------------
        if (elect_one()) {
            int st = 0, ph = 1;
            for (int k = 0; k < KITERS; k++) {
                MBARRIER_WAIT_PARITY(sb + MB_EMPTY + 8 * st, ph);
                MBARRIER_EXPECT_TX(sb + MB_FULL + 8 * st, STAGE_BYTES);
                uint32_t abase = sb + SMEM_TILE0 + st * STAGE_BYTES;
                tma_load_2d(abase, &tmA, k * KC, mtile * MT, sb + MB_FULL + 8 * st);
                tma_load_2d(abase + A_BYTES, &tmB, k * KC, ntile * NT, sb + MB_FULL + 8 * st);
                if (++st == STAGES) { st = 0; ph ^= 1; }
            }
        }
        return;
    }

    // ---------------- compute warps ----------------
    const int mw = (wid >> 2) * 64;   // 0 / 64
    const int nw = (wid & 3) * 64;    // 0..192
    const int g = lane >> 2;          // 0..7
    const int q = lane & 3;           // 0..3
    const int xorv = g * 4;

    float acc[4][8][4];
    #pragma unroll
    for (int tm = 0; tm < 4; tm++)
        #pragma unroll
        for (int tn = 0; tn < 8; tn++)
            #pragma unroll
            for (int r = 0; r < 4; r++) acc[tm][tn][r] = 0.0f;

    int st = 0, ph = 0;
    for (int k = 0; k < KITERS; k++) {
        // warp-elected wait: lane0 acquires, warp-sync propagates ordering
        if (elect_one()) MBARRIER_WAIT_PARITY(sb + MB_FULL + 8 * st, ph);
        __syncwarp();

        uint32_t sa = sb + SMEM_TILE0 + st * STAGE_BYTES;
        uint32_t sbB = sa + A_BYTES;
        uint32_t aRow = sa + (mw + g) * 128;
        uint32_t bRow = sbB + (nw + g) * 128;

        #pragma unroll
        for (int kk = 0; kk < 4; kk++) {
            const int kkk = kk * 8;
            const uint32_t c0 = (uint32_t)(((kkk + q) ^ xorv) << 2);
            const uint32_t c1 = (uint32_t)(((kkk + 4 + q) ^ xorv) << 2);

            uint32_t afr[4][4];
            #pragma unroll
            for (int tm = 0; tm < 4; tm++) {
                uint32_t base = aRow + tm * 2048;           // 16 rows * 128B
                afr[tm][0] = lds32(base + c0);
                afr[tm][1] = lds32(base + 1024 + c0);       // +8 rows
                afr[tm][2] = lds32(base + c1);
                afr[tm][3] = lds32(base + 1024 + c1);
            }
            uint32_t bfr[8][2];
            #pragma unroll
            for (int tn = 0; tn < 8; tn++) {
                uint32_t base = bRow + tn * 1024;           // 8 rows * 128B
                bfr[tn][0] = lds32(base + c0);
                bfr[tn][1] = lds32(base + c1);
            }
            #pragma unroll
            for (int tm = 0; tm < 4; tm++)
                #pragma unroll
                for (int tn = 0; tn < 8; tn++)
                    mma_tf32(acc[tm][tn], afr[tm], bfr[tn]);
        }

        // warp-elected arrive: by mma issue, all this warp's stage-LDS completed
        if (elect_one()) MBARRIER_ARRIVE(sb + MB_EMPTY + 8 * st);
        if (++st == STAGES) { st = 0; ph ^= 1; }
    }

    // ---------------- epilogue ----------------
    #pragma unroll
    for (int tm = 0; tm < 4; tm++) {
        const int row0 = mtile * MT + mw + tm * 16 + g;
        #pragma unroll
        for (int tn = 0; tn < 8; tn++) {
            const int col = ntile * NT + nw + tn * 8 + 2 * q;
            float2 lo = make_float2(acc[tm][tn][0], acc[tm][tn][1]);
            float2 hi = make_float2(acc[tm][tn][2], acc[tm][tn][3]);
            *reinterpret_cast<float2*>(out + (size_t)row0 * N_ALL + col) = lo;
            *reinterpret_cast<float2*>(out + (size_t)(row0 + 8) * N_ALL + col) = hi;
        }
    }
}

// ---------------------------------------------------------------------------
typedef CUresult (*EncodeFn)(CUtensorMap*, CUtensorMapDataType, cuuint32_t, void*,
                             const cuuint64_t*, const cuuint64_t*, const cuuint32_t*,
                             const cuuint32_t*, CUtensorMapInterleave, CUtensorMapSwizzle,
                             CUtensorMapL2promotion, CUtensorMapFloatOOBfill);

extern "C" void kernel_launch(void* const* d_in, const int* in_sizes, int n_in,
                              void* d_out, int out_size) {
    const float* x  = (const float*)d_in[0];
    const float* W  = (const float*)d_in[1];
    const float* lA = (const float*)d_in[2];
    const float* lB = (const float*)d_in[3];
    float* out = (float*)d_out;

    void* xr = nullptr;
    void* wf = nullptr;
    cudaGetSymbolAddress(&xr, g_xr);
    cudaGetSymbolAddress(&wf, g_weff);

    void* h = dlopen("libcuda.so.1", RTLD_LAZY | RTLD_GLOBAL);
    if (!h) h = dlopen("libcuda.so", RTLD_LAZY | RTLD_GLOBAL);
    EncodeFn enc = h ? (EncodeFn)dlsym(h, "cuTensorMapEncodeTiled") : nullptr;
    if (!enc || !xr || !wf) return;

    CUtensorMap tmA{}, tmB{};
    {
        cuuint64_t dims[2] = {(cuuint64_t)K_ALL, (cuuint64_t)M_ALL};
        cuuint64_t str[1]  = {(cuuint64_t)K_ALL * 4};
        cuuint32_t box[2]  = {(cuuint32_t)KC, (cuuint32_t)MT};
        cuuint32_t es[2]   = {1, 1};
        enc(&tmA, CU_TENSOR_MAP_DATA_TYPE_FLOAT32, 2, xr, dims, str, box, es,
            CU_TENSOR_MAP_INTERLEAVE_NONE, CU_TENSOR_MAP_SWIZZLE_128B,
            CU_TENSOR_MAP_L2_PROMOTION_L2_128B, CU_TENSOR_MAP_FLOAT_OOB_FILL_NONE);
    }
    {
        cuuint64_t dims[2] = {(cuuint64_t)K_ALL, (cuuint64_t)N_ALL};
        cuuint64_t str[1]  = {(cuuint64_t)K_ALL * 4};
        cuuint32_t box[2]  = {(cuuint32_t)KC, (cuuint32_t)NT};
        cuuint32_t es[2]   = {1, 1};
        enc(&tmB, CU_TENSOR_MAP_DATA_TYPE_FLOAT32, 2, wf, dims, str, box, es,
            CU_TENSOR_MAP_INTERLEAVE_NONE, CU_TENSOR_MAP_SWIZZLE_128B,
            CU_TENSOR_MAP_L2_PROMOTION_L2_128B, CU_TENSOR_MAP_FLOAT_OOB_FILL_NONE);
    }

    cudaFuncSetAttribute(gemm_tf32, cudaFuncAttributeMaxDynamicSharedMemorySize, SMEM_TOTAL);

    prep_x<<<(M_ALL * K_ALL / 4) / 256, 256>>>(x);
    prep_w<<<N_ALL, 256>>>(W, lA, lB);

    dim3 grid(N_ALL / NT, M_ALL / MT); // (16, 64)
    gemm_tf32<<<grid, 288, SMEM_TOTAL>>>(tmA, tmB, out);
}